// round 14
// baseline (speedup 1.0000x reference)
#include <cuda_runtime.h>

#define N_NODES 100000
#define N_EDGES 1600000
#define HID 64
#define EDIM 32
#define MAXDEG 64
#define N_LAYERS 3
#define BN_EPS 1e-5f
#define NPW 8   // nodes per warp in agg

typedef unsigned long long u64;

// ---------------- scratch (static device globals; no allocation) ----------------
__device__ float g_agg[(size_t)N_NODES * HID];
__device__ float g_tmp[(size_t)N_NODES * HID];
__device__ float g_bufA[(size_t)N_NODES * HID];
__device__ float g_bufB[(size_t)N_NODES * HID];
__device__ float g_stats[N_LAYERS * 2 * HID];
__device__ int   g_deg[N_NODES];
__device__ int   g_src[(size_t)N_NODES * MAXDEG];
__device__ float g_attr_p[(size_t)N_NODES * MAXDEG * EDIM];

__device__ __forceinline__ const float* sel_x(const float* xext, int sel) {
    return sel == 0 ? xext : (sel == 1 ? (const float*)g_bufA : (const float*)g_bufB);
}

// ---------------- packed f32x2 helpers ----------------
__device__ __forceinline__ u64 pk(float s) {
    u64 r; asm("mov.b64 %0, {%1, %1};" : "=l"(r) : "f"(s)); return r;
}
__device__ __forceinline__ u64 pk2(float a, float b) {
    u64 r; asm("mov.b64 %0, {%1, %2};" : "=l"(r) : "f"(a), "f"(b)); return r;
}
__device__ __forceinline__ void fma2(u64& d, u64 a, u64 b) {
    asm("fma.rn.f32x2 %0, %1, %2, %0;" : "+l"(d) : "l"(a), "l"(b));
}
__device__ __forceinline__ void unpk(u64 v, float& lo, float& hi) {
    asm("mov.b64 {%0, %1}, %2;" : "=f"(lo), "=f"(hi) : "l"(v));
}
__device__ __forceinline__ float hsum2(u64 v) {
    float lo, hi; unpk(v, lo, hi); return lo + hi;
}

// ---------------- cp.async helpers ----------------
__device__ __forceinline__ void cp16(unsigned dst, const void* src) {
    asm volatile("cp.async.cg.shared.global [%0], [%1], 16;" :: "r"(dst), "l"(src));
}
__device__ __forceinline__ void cp_commit() { asm volatile("cp.async.commit_group;"); }

// ---------------- init ----------------
__global__ void zero_kernel() {
    int i = blockIdx.x * blockDim.x + threadIdx.x;
    if (i < N_NODES) g_deg[i] = 0;
    if (i < N_LAYERS * 2 * HID) g_stats[i] = 0.0f;
}

// ---------------- CSR build + attr permutation fused (once per launch) ----------------
__global__ void __launch_bounds__(256) csr_perm_kernel(
    const int* __restrict__ ei, const float* __restrict__ attr)
{
    int t = blockIdx.x * 256 + threadIdx.x;
    int e = t >> 3, q = t & 7;
    if (e >= N_EDGES) return;
    int dst = 0, slot = 0;
    if (q == 0) {
        dst = ei[N_EDGES + e];
        slot = atomicAdd(&g_deg[dst], 1);
    }
    dst  = __shfl_sync(0xffffffffu, dst, 0, 8);
    slot = __shfl_sync(0xffffffffu, slot, 0, 8);
    if (slot < MAXDEG) {
        int d = dst * MAXDEG + slot;
        if (q == 0) g_src[d] = ei[e];
        ((float4*)g_attr_p)[(size_t)d * 8 + q] =
            __ldg((const float4*)attr + (size_t)e * 8 + q);
    }
}

// ---------------- edge aggregation: warp owns NPW nodes; cross-node sub-chunk pipeline ----
__global__ void __launch_bounds__(128, 4) agg_kernel(
    const float* __restrict__ xext, int xsel,
    const float* __restrict__ We, const float* __restrict__ be)
{
    __shared__ __align__(16) float sAttr[4][2][16 * 32];   // 2KB / buf / warp
    __shared__ __align__(16) float sX[4][2][16 * 64];      // 4KB / buf / warp

    int wid  = threadIdx.x >> 5;
    int lane = threadIdx.x & 31;
    int nodeBeg = (blockIdx.x * 4 + wid) * NPW;
    int nodeEnd = nodeBeg + NPW;                            // N divisible by 32*NPW? 100000/32=3125 ✓

    const char* xg = (const char*)sel_x(xext, xsel);
    int fA = 2 * lane, fB = 2 * lane + 1;

    u64 wA[16], wB[16];
#pragma unroll
    for (int kp = 0; kp < 16; kp++) {
        wA[kp] = pk2(__ldg(We + (2 * kp) * HID + fA), __ldg(We + (2 * kp + 1) * HID + fA));
        wB[kp] = pk2(__ldg(We + (2 * kp) * HID + fB), __ldg(We + (2 * kp + 1) * HID + fB));
    }
    u64 biasA = pk2(__ldg(be + fA), 0.0f);
    u64 biasB = pk2(__ldg(be + fB), 0.0f);

    // total sub-chunks for this warp (lane-parallel count + butterfly reduce)
    int dd = (lane < NPW) ? min(g_deg[nodeBeg + lane], MAXDEG) : 0;
    int S = (dd + 15) >> 4;
#pragma unroll
    for (int o = 16; o > 0; o >>= 1) S += __shfl_xor_sync(0xffffffffu, S, o);

    unsigned abuf0 = (unsigned)__cvta_generic_to_shared(&sAttr[wid][0][0]);
    unsigned abuf1 = (unsigned)__cvta_generic_to_shared(&sAttr[wid][1][0]);
    unsigned xbuf0 = (unsigned)__cvta_generic_to_shared(&sX[wid][0][0]);
    unsigned xbuf1 = (unsigned)__cvta_generic_to_shared(&sX[wid][1][0]);

    // ---- stage cursor ----
    int sN = nodeBeg, sO = 0, sD = 0;
    while (sN < nodeEnd) { sD = min(g_deg[sN], MAXDEG); if (sD > 0) break; sN++; }

    auto stageNext = [&](int b) {
        int cnt = sD - sO; if (cnt > 16) cnt = 16;
        unsigned ab = b ? abuf1 : abuf0;
        unsigned xb = b ? xbuf1 : xbuf0;
        const char* asrc = (const char*)g_attr_p + ((size_t)sN * MAXDEG + sO) * 128;
        int words = cnt * 8;
        for (int i = lane; i < words; i += 32)
            cp16(ab + i * 16, asrc + i * 16);
        int p = lane >> 1, hh = lane & 1;        // 2 lanes per edge, 128B each
        if (p < cnt) {
            int src = g_src[sN * MAXDEG + sO + p];
            const char* xs = xg + (size_t)src * 256 + hh * 128;
            unsigned xd = xb + p * 256 + hh * 128;
#pragma unroll
            for (int i = 0; i < 8; i++) cp16(xd + i * 16, xs + i * 16);
        }
        cp_commit();
        sO += 16;
        if (sO >= sD) {
            sO = 0; sN++;
            while (sN < nodeEnd) { sD = min(g_deg[sN], MAXDEG); if (sD > 0) break; sN++; }
        }
    };

    // ---- compute cursor ----
    float accx = 0.0f, accy = 0.0f;
    float2 zero2; zero2.x = 0.0f; zero2.y = 0.0f;
    int cN = nodeBeg, cO = 0, cD = 0;
    while (cN < nodeEnd) {
        cD = min(g_deg[cN], MAXDEG);
        if (cD > 0) break;
        ((float2*)g_agg)[(size_t)cN * 32 + lane] = zero2;   // deg-0 node
        cN++;
    }

    auto computeOne = [&](int b) {
        int cnt = cD - cO; if (cnt > 16) cnt = 16;
        const ulonglong2* Abuf = (const ulonglong2*)&sAttr[wid][b][0];
        const u64* Xbuf = (const u64*)&sX[wid][b][0];
        int j = 0;
        for (; j + 4 <= cnt; j += 4) {
            u64 a0A = biasA, a0B = biasB, a1A = biasA, a1B = biasB;
            u64 a2A = biasA, a2B = biasB, a3A = biasA, a3B = biasB;
#pragma unroll
            for (int c = 0; c < 8; c++) {
                ulonglong2 p0 = Abuf[(j + 0) * 8 + c];
                ulonglong2 p1 = Abuf[(j + 1) * 8 + c];
                ulonglong2 p2 = Abuf[(j + 2) * 8 + c];
                ulonglong2 p3 = Abuf[(j + 3) * 8 + c];
                fma2(a0A, p0.x, wA[2 * c]);     fma2(a0B, p0.x, wB[2 * c]);
                fma2(a0A, p0.y, wA[2 * c + 1]); fma2(a0B, p0.y, wB[2 * c + 1]);
                fma2(a1A, p1.x, wA[2 * c]);     fma2(a1B, p1.x, wB[2 * c]);
                fma2(a1A, p1.y, wA[2 * c + 1]); fma2(a1B, p1.y, wB[2 * c + 1]);
                fma2(a2A, p2.x, wA[2 * c]);     fma2(a2B, p2.x, wB[2 * c]);
                fma2(a2A, p2.y, wA[2 * c + 1]); fma2(a2B, p2.y, wB[2 * c + 1]);
                fma2(a3A, p3.x, wA[2 * c]);     fma2(a3B, p3.x, wB[2 * c]);
                fma2(a3A, p3.y, wA[2 * c + 1]); fma2(a3B, p3.y, wB[2 * c + 1]);
            }
            float xl, xh;
            unpk(Xbuf[(j + 0) * 32 + lane], xl, xh);
            accx += fmaxf(xl + hsum2(a0A), 0.0f); accy += fmaxf(xh + hsum2(a0B), 0.0f);
            unpk(Xbuf[(j + 1) * 32 + lane], xl, xh);
            accx += fmaxf(xl + hsum2(a1A), 0.0f); accy += fmaxf(xh + hsum2(a1B), 0.0f);
            unpk(Xbuf[(j + 2) * 32 + lane], xl, xh);
            accx += fmaxf(xl + hsum2(a2A), 0.0f); accy += fmaxf(xh + hsum2(a2B), 0.0f);
            unpk(Xbuf[(j + 3) * 32 + lane], xl, xh);
            accx += fmaxf(xl + hsum2(a3A), 0.0f); accy += fmaxf(xh + hsum2(a3B), 0.0f);
        }
        for (; j < cnt; j++) {
            u64 a0A = biasA, a0B = biasB;
#pragma unroll
            for (int c = 0; c < 8; c++) {
                ulonglong2 p0 = Abuf[j * 8 + c];
                fma2(a0A, p0.x, wA[2 * c]);     fma2(a0B, p0.x, wB[2 * c]);
                fma2(a0A, p0.y, wA[2 * c + 1]); fma2(a0B, p0.y, wB[2 * c + 1]);
            }
            float xl, xh;
            unpk(Xbuf[j * 32 + lane], xl, xh);
            accx += fmaxf(xl + hsum2(a0A), 0.0f); accy += fmaxf(xh + hsum2(a0B), 0.0f);
        }
        cO += 16;
        if (cO >= cD) {
            float2 o; o.x = accx; o.y = accy;
            ((float2*)g_agg)[(size_t)cN * 32 + lane] = o;
            accx = 0.0f; accy = 0.0f;
            cO = 0; cN++;
            while (cN < nodeEnd) {
                cD = min(g_deg[cN], MAXDEG);
                if (cD > 0) break;
                ((float2*)g_agg)[(size_t)cN * 32 + lane] = zero2;  // deg-0 node
                cN++;
            }
        }
    };

    if (S > 0) {
        stageNext(0);
        for (int s = 0; s < S; s++) {
            if (s + 1 < S) {
                stageNext((s + 1) & 1);
                asm volatile("cp.async.wait_group 1;" ::: "memory");
            } else {
                asm volatile("cp.async.wait_group 0;" ::: "memory");
            }
            __syncwarp();
            computeOne(s & 1);
            __syncwarp();   // reads done before buffer restaged
        }
    }
}

// ---------------- node MLP + fused BN partial stats: 128 rows / 128 threads ----------------
#define SH(r, c) ((r) * 64 + ((c) ^ ((r) & 31)))

__global__ void __launch_bounds__(128, 4) mlp_kernel(
    const float* __restrict__ xext, int xsel,
    const float* __restrict__ W1, const float* __restrict__ b1,
    const float* __restrict__ W2, const float* __restrict__ b2, int layer)
{
    __shared__ float sh[128 * 64];
    __shared__ ulonglong2 sW[64 * 16];
    const float* x = sel_x(xext, xsel);
    int tid = threadIdx.x;
    int rowbase = blockIdx.x * 128;

    for (int i = tid; i < 128 * 64; i += 128) {
        int r = i >> 6, c = i & 63;
        float v = 0.0f;
        if (rowbase + r < N_NODES) {
            size_t g = (size_t)(rowbase + r) * HID + c;
            v = x[g] + g_agg[g];
        }
        sh[SH(r, c)] = v;
    }
    for (int i = tid; i < 1024; i += 128) sW[i] = ((const ulonglong2*)W1)[i];
    __syncthreads();

    u64 acc[32];
#pragma unroll
    for (int j = 0; j < 32; j++) acc[j] = ((const u64*)b1)[j];
    for (int k = 0; k < 64; k++) {
        u64 hk = pk(sh[SH(tid, k)]);
#pragma unroll 4
        for (int j = 0; j < 16; j++) {
            ulonglong2 wv = sW[k * 16 + j];
            fma2(acc[2 * j], hk, wv.x);
            fma2(acc[2 * j + 1], hk, wv.y);
        }
    }
    __syncthreads();
#pragma unroll
    for (int j = 0; j < 32; j++) {
        float lo, hi; unpk(acc[j], lo, hi);
        sh[SH(tid, 2 * j)]     = fmaxf(lo, 0.0f);
        sh[SH(tid, 2 * j + 1)] = fmaxf(hi, 0.0f);
    }
    for (int i = tid; i < 1024; i += 128) sW[i] = ((const ulonglong2*)W2)[i];
    __syncthreads();

#pragma unroll
    for (int j = 0; j < 32; j++) acc[j] = ((const u64*)b2)[j];
    for (int k = 0; k < 64; k++) {
        u64 hk = pk(sh[SH(tid, k)]);
#pragma unroll 4
        for (int j = 0; j < 16; j++) {
            ulonglong2 wv = sW[k * 16 + j];
            fma2(acc[2 * j], hk, wv.x);
            fma2(acc[2 * j + 1], hk, wv.y);
        }
    }
#pragma unroll
    for (int j = 0; j < 32; j++) {
        float lo, hi; unpk(acc[j], lo, hi);
        sh[SH(tid, 2 * j)]     = lo;
        sh[SH(tid, 2 * j + 1)] = hi;
    }
    __syncthreads();

    for (int i = tid; i < 128 * 64; i += 128) {
        int r = i >> 6, c = i & 63;
        if (rowbase + r < N_NODES)
            g_tmp[(size_t)(rowbase + r) * HID + c] = sh[SH(r, c)];
    }

    {
        float* red = (float*)sW;
        int f = tid & 63, half = tid >> 6;
        float s = 0.0f, s2 = 0.0f;
        int rend = half * 64 + 64;
        for (int r = half * 64; r < rend; r++) {
            if (rowbase + r < N_NODES) {
                float v = sh[SH(r, f)];
                s += v; s2 += v * v;
            }
        }
        red[tid] = s;
        red[128 + tid] = s2;
        __syncthreads();
        if (tid < 64) {
            atomicAdd(&g_stats[layer * 128 + f],      red[tid] + red[tid + 64]);
            atomicAdd(&g_stats[layer * 128 + 64 + f], red[128 + tid] + red[192 + tid]);
        }
    }
}

// ---------------- BN apply + relu -> next layer's x buffer (layers 0,1) --------------------
__global__ void __launch_bounds__(256) bn_kernel(
    int layer, const float* __restrict__ gamma, const float* __restrict__ beta, int outsel)
{
    size_t idx = (size_t)blockIdx.x * 256 + threadIdx.x;
    if (idx >= (size_t)N_NODES * HID) return;
    int f = (int)(idx & 63);
    const float inv = 1.0f / (float)N_NODES;
    float mean = g_stats[layer * 128 + f] * inv;
    float var  = g_stats[layer * 128 + 64 + f] * inv - mean * mean;
    float v = (g_tmp[idx] - mean) * rsqrtf(var + BN_EPS) * __ldg(gamma + f) + __ldg(beta + f);
    float* o = (outsel == 1) ? g_bufA : g_bufB;
    o[idx] = fmaxf(v, 0.0f);
}

// ---------------- output head with fused layer-2 BN ----------------------------------------
__global__ void __launch_bounds__(128, 4) out_kernel(
    const float* __restrict__ Wout, const float* __restrict__ bout,
    const float* __restrict__ gamma2, const float* __restrict__ beta2,
    float* __restrict__ out)
{
    __shared__ float sh[128 * 64];
    __shared__ ulonglong2 sW[64 * 16];
    int tid = threadIdx.x;
    int rowbase = blockIdx.x * 128;

    int fc = tid & 63;
    const float inv = 1.0f / (float)N_NODES;
    float mean = g_stats[2 * 128 + fc] * inv;
    float var  = g_stats[2 * 128 + 64 + fc] * inv - mean * mean;
    float rs   = rsqrtf(var + BN_EPS) * __ldg(gamma2 + fc);
    float bt   = __ldg(beta2 + fc);

    for (int i = tid; i < 128 * 64; i += 128) {
        int r = i >> 6, c = i & 63;
        float v = 0.0f;
        if (rowbase + r < N_NODES) {
            float t = g_tmp[(size_t)(rowbase + r) * HID + c];
            v = fmaxf((t - mean) * rs + bt, 0.0f);
        }
        sh[SH(r, c)] = v;
    }
    for (int i = tid; i < 1024; i += 128) sW[i] = ((const ulonglong2*)Wout)[i];
    __syncthreads();

    u64 acc[32];
#pragma unroll
    for (int j = 0; j < 32; j++) acc[j] = ((const u64*)bout)[j];
    for (int k = 0; k < 64; k++) {
        u64 hk = pk(sh[SH(tid, k)]);
#pragma unroll 4
        for (int j = 0; j < 16; j++) {
            ulonglong2 wv = sW[k * 16 + j];
            fma2(acc[2 * j], hk, wv.x);
            fma2(acc[2 * j + 1], hk, wv.y);
        }
    }
    __syncthreads();
#pragma unroll
    for (int j = 0; j < 32; j++) {
        float lo, hi; unpk(acc[j], lo, hi);
        sh[SH(tid, 2 * j)]     = lo;
        sh[SH(tid, 2 * j + 1)] = hi;
    }
    __syncthreads();
    for (int i = tid; i < 128 * 64; i += 128) {
        int r = i >> 6, c = i & 63;
        if (rowbase + r < N_NODES)
            out[(size_t)(rowbase + r) * HID + c] = sh[SH(r, c)];
    }
}

// ---------------- launch --------------------------------------------------------------------
extern "C" void kernel_launch(void* const* d_in, const int* in_sizes, int n_in,
                              void* d_out, int out_size) {
    const float* x     = (const float*)d_in[0];
    const int*   ei    = (const int*)  d_in[1];
    const float* ea    = (const float*)d_in[2];
    const float* We    = (const float*)d_in[3];
    const float* be    = (const float*)d_in[4];
    const float* W1    = (const float*)d_in[5];
    const float* b1    = (const float*)d_in[6];
    const float* W2    = (const float*)d_in[7];
    const float* b2    = (const float*)d_in[8];
    const float* gamma = (const float*)d_in[9];
    const float* beta  = (const float*)d_in[10];
    const float* Wout  = (const float*)d_in[11];
    const float* bout  = (const float*)d_in[12];
    float* out = (float*)d_out;

    const int AGG_BLOCKS  = N_NODES / (4 * NPW);                 // 3125 (exact)
    const int MLP_BLOCKS  = (N_NODES + 127) / 128;
    const int BN_BLOCKS   = (int)(((size_t)N_NODES * HID + 255) / 256);
    const int CSR_BLOCKS  = (N_EDGES * 8 + 255) / 256;

    zero_kernel<<<(N_NODES + 255) / 256, 256>>>();
    csr_perm_kernel<<<CSR_BLOCKS, 256>>>(ei, ea);

    agg_kernel<<<AGG_BLOCKS, 128>>>(x, 0, We + 0 * EDIM * HID, be + 0 * HID);
    mlp_kernel<<<MLP_BLOCKS, 128>>>(x, 0, W1 + 0 * HID * HID, b1 + 0 * HID,
                                    W2 + 0 * HID * HID, b2 + 0 * HID, 0);
    bn_kernel<<<BN_BLOCKS, 256>>>(0, gamma + 0 * HID, beta + 0 * HID, 1);

    agg_kernel<<<AGG_BLOCKS, 128>>>(x, 1, We + 1 * EDIM * HID, be + 1 * HID);
    mlp_kernel<<<MLP_BLOCKS, 128>>>(x, 1, W1 + 1 * HID * HID, b1 + 1 * HID,
                                    W2 + 1 * HID * HID, b2 + 1 * HID, 1);
    bn_kernel<<<BN_BLOCKS, 256>>>(1, gamma + 1 * HID, beta + 1 * HID, 2);

    agg_kernel<<<AGG_BLOCKS, 128>>>(x, 2, We + 2 * EDIM * HID, be + 2 * HID);
    mlp_kernel<<<MLP_BLOCKS, 128>>>(x, 2, W1 + 2 * HID * HID, b1 + 2 * HID,
                                    W2 + 2 * HID * HID, b2 + 2 * HID, 2);

    out_kernel<<<MLP_BLOCKS, 128>>>(Wout, bout, gamma + 2 * HID, beta + 2 * HID, out);
}

// round 15
// speedup vs baseline: 2.9336x; 2.9336x over previous
#include <cuda_runtime.h>

#define N_NODES 100000
#define N_EDGES 1600000
#define HID 64
#define EDIM 32
#define MAXDEG 64
#define N_LAYERS 3
#define BN_EPS 1e-5f
#define NPW 8   // nodes per warp in agg

typedef unsigned long long u64;

// ---------------- scratch (static device globals; no allocation) ----------------
__device__ float g_agg[(size_t)N_NODES * HID];
__device__ float g_tmp[(size_t)N_NODES * HID];
__device__ float g_bufA[(size_t)N_NODES * HID];
__device__ float g_bufB[(size_t)N_NODES * HID];
__device__ float g_stats[N_LAYERS * 2 * HID];
__device__ int   g_deg[N_NODES];
__device__ int   g_src[(size_t)N_NODES * MAXDEG];
__device__ float g_attr_p[(size_t)N_NODES * MAXDEG * EDIM];

__device__ __forceinline__ const float* sel_x(const float* xext, int sel) {
    return sel == 0 ? xext : (sel == 1 ? (const float*)g_bufA : (const float*)g_bufB);
}

// ---------------- packed f32x2 helpers ----------------
__device__ __forceinline__ u64 pk(float s) {
    u64 r; asm("mov.b64 %0, {%1, %1};" : "=l"(r) : "f"(s)); return r;
}
__device__ __forceinline__ u64 pk2(float a, float b) {
    u64 r; asm("mov.b64 %0, {%1, %2};" : "=l"(r) : "f"(a), "f"(b)); return r;
}
__device__ __forceinline__ void fma2(u64& d, u64 a, u64 b) {
    asm("fma.rn.f32x2 %0, %1, %2, %0;" : "+l"(d) : "l"(a), "l"(b));
}
__device__ __forceinline__ void unpk(u64 v, float& lo, float& hi) {
    asm("mov.b64 {%0, %1}, %2;" : "=f"(lo), "=f"(hi) : "l"(v));
}
__device__ __forceinline__ float hsum2(u64 v) {
    float lo, hi; unpk(v, lo, hi); return lo + hi;
}

// ---------------- cp.async helpers ----------------
__device__ __forceinline__ void cp16(unsigned dst, const void* src) {
    asm volatile("cp.async.cg.shared.global [%0], [%1], 16;" :: "r"(dst), "l"(src));
}
__device__ __forceinline__ void cp_commit() { asm volatile("cp.async.commit_group;"); }

// ---------------- init ----------------
__global__ void zero_kernel() {
    int i = blockIdx.x * blockDim.x + threadIdx.x;
    if (i < N_NODES) g_deg[i] = 0;
    if (i < N_LAYERS * 2 * HID) g_stats[i] = 0.0f;
}

// ---------------- CSR build + attr permutation fused (once per launch) ----------------
__global__ void __launch_bounds__(256) csr_perm_kernel(
    const int* __restrict__ ei, const float* __restrict__ attr)
{
    int t = blockIdx.x * 256 + threadIdx.x;
    int e = t >> 3, q = t & 7;
    if (e >= N_EDGES) return;
    int dst = 0, slot = 0;
    if (q == 0) {
        dst = ei[N_EDGES + e];
        slot = atomicAdd(&g_deg[dst], 1);
    }
    dst  = __shfl_sync(0xffffffffu, dst, 0, 8);
    slot = __shfl_sync(0xffffffffu, slot, 0, 8);
    if (slot < MAXDEG) {
        int d = dst * MAXDEG + slot;
        if (q == 0) g_src[d] = ei[e];
        ((float4*)g_attr_p)[(size_t)d * 8 + q] =
            __ldg((const float4*)attr + (size_t)e * 8 + q);
    }
}

// ---------------- edge aggregation: warp owns NPW nodes; cross-node sub-chunk pipeline ----
__global__ void __launch_bounds__(128, 4) agg_kernel(
    const float* __restrict__ xext, int xsel,
    const float* __restrict__ We, const float* __restrict__ be)
{
    __shared__ __align__(16) float sAttr[4][2][16 * 32];   // 2KB / buf / warp
    __shared__ __align__(16) float sX[4][2][16 * 64];      // 4KB / buf / warp

    int wid  = threadIdx.x >> 5;
    int lane = threadIdx.x & 31;
    int nodeBeg = (blockIdx.x * 4 + wid) * NPW;
    int nodeEnd = nodeBeg + NPW;

    const char* xg = (const char*)sel_x(xext, xsel);
    int fA = 2 * lane, fB = 2 * lane + 1;

    u64 wA[16], wB[16];
#pragma unroll
    for (int kp = 0; kp < 16; kp++) {
        wA[kp] = pk2(__ldg(We + (2 * kp) * HID + fA), __ldg(We + (2 * kp + 1) * HID + fA));
        wB[kp] = pk2(__ldg(We + (2 * kp) * HID + fB), __ldg(We + (2 * kp + 1) * HID + fB));
    }
    u64 biasA = pk2(__ldg(be + fA), 0.0f);
    u64 biasB = pk2(__ldg(be + fB), 0.0f);

    // total sub-chunks for this warp (lane-parallel count + butterfly reduce)
    int dd = (lane < NPW) ? min(g_deg[nodeBeg + lane], MAXDEG) : 0;
    int S = (dd + 15) >> 4;
#pragma unroll
    for (int o = 16; o > 0; o >>= 1) S += __shfl_xor_sync(0xffffffffu, S, o);

    unsigned abuf0 = (unsigned)__cvta_generic_to_shared(&sAttr[wid][0][0]);
    unsigned abuf1 = (unsigned)__cvta_generic_to_shared(&sAttr[wid][1][0]);
    unsigned xbuf0 = (unsigned)__cvta_generic_to_shared(&sX[wid][0][0]);
    unsigned xbuf1 = (unsigned)__cvta_generic_to_shared(&sX[wid][1][0]);

    // ---- stage cursor ----
    int sN = nodeBeg, sO = 0, sD = 0;
    while (sN < nodeEnd) { sD = min(g_deg[sN], MAXDEG); if (sD > 0) break; sN++; }

    auto stageNext = [&](int b) {
        int cnt = sD - sO; if (cnt > 16) cnt = 16;
        unsigned ab = b ? abuf1 : abuf0;
        unsigned xb = b ? xbuf1 : xbuf0;
        const char* asrc = (const char*)g_attr_p + ((size_t)sN * MAXDEG + sO) * 128;
        int words = cnt * 8;
        for (int i = lane; i < words; i += 32)
            cp16(ab + i * 16, asrc + i * 16);
        int p = lane >> 1, hh = lane & 1;        // 2 lanes per edge, 128B each
        if (p < cnt) {
            int src = g_src[sN * MAXDEG + sO + p];
            const char* xs = xg + (size_t)src * 256 + hh * 128;
            unsigned xd = xb + p * 256 + hh * 128;
#pragma unroll
            for (int i = 0; i < 8; i++) cp16(xd + i * 16, xs + i * 16);
        }
        cp_commit();
        sO += 16;
        if (sO >= sD) {
            sO = 0; sN++;
            while (sN < nodeEnd) { sD = min(g_deg[sN], MAXDEG); if (sD > 0) break; sN++; }
        }
    };

    // ---- compute cursor ----
    float accx = 0.0f, accy = 0.0f;
    float2 zero2; zero2.x = 0.0f; zero2.y = 0.0f;
    int cN = nodeBeg, cO = 0, cD = 0;
    while (cN < nodeEnd) {
        cD = min(g_deg[cN], MAXDEG);
        if (cD > 0) break;
        ((float2*)g_agg)[(size_t)cN * 32 + lane] = zero2;   // deg-0 node
        cN++;
    }

    auto computeOne = [&](int b) {
        int cnt = cD - cO; if (cnt > 16) cnt = 16;
        const ulonglong2* Abuf = (const ulonglong2*)&sAttr[wid][b][0];
        const u64* Xbuf = (const u64*)&sX[wid][b][0];
        int j = 0;
        for (; j + 4 <= cnt; j += 4) {
            u64 a0A = biasA, a0B = biasB, a1A = biasA, a1B = biasB;
            u64 a2A = biasA, a2B = biasB, a3A = biasA, a3B = biasB;
#pragma unroll
            for (int c = 0; c < 8; c++) {
                ulonglong2 p0 = Abuf[(j + 0) * 8 + c];
                ulonglong2 p1 = Abuf[(j + 1) * 8 + c];
                ulonglong2 p2 = Abuf[(j + 2) * 8 + c];
                ulonglong2 p3 = Abuf[(j + 3) * 8 + c];
                fma2(a0A, p0.x, wA[2 * c]);     fma2(a0B, p0.x, wB[2 * c]);
                fma2(a0A, p0.y, wA[2 * c + 1]); fma2(a0B, p0.y, wB[2 * c + 1]);
                fma2(a1A, p1.x, wA[2 * c]);     fma2(a1B, p1.x, wB[2 * c]);
                fma2(a1A, p1.y, wA[2 * c + 1]); fma2(a1B, p1.y, wB[2 * c + 1]);
                fma2(a2A, p2.x, wA[2 * c]);     fma2(a2B, p2.x, wB[2 * c]);
                fma2(a2A, p2.y, wA[2 * c + 1]); fma2(a2B, p2.y, wB[2 * c + 1]);
                fma2(a3A, p3.x, wA[2 * c]);     fma2(a3B, p3.x, wB[2 * c]);
                fma2(a3A, p3.y, wA[2 * c + 1]); fma2(a3B, p3.y, wB[2 * c + 1]);
            }
            float xl, xh;
            unpk(Xbuf[(j + 0) * 32 + lane], xl, xh);
            accx += fmaxf(xl + hsum2(a0A), 0.0f); accy += fmaxf(xh + hsum2(a0B), 0.0f);
            unpk(Xbuf[(j + 1) * 32 + lane], xl, xh);
            accx += fmaxf(xl + hsum2(a1A), 0.0f); accy += fmaxf(xh + hsum2(a1B), 0.0f);
            unpk(Xbuf[(j + 2) * 32 + lane], xl, xh);
            accx += fmaxf(xl + hsum2(a2A), 0.0f); accy += fmaxf(xh + hsum2(a2B), 0.0f);
            unpk(Xbuf[(j + 3) * 32 + lane], xl, xh);
            accx += fmaxf(xl + hsum2(a3A), 0.0f); accy += fmaxf(xh + hsum2(a3B), 0.0f);
        }
        for (; j < cnt; j++) {
            u64 a0A = biasA, a0B = biasB;
#pragma unroll
            for (int c = 0; c < 8; c++) {
                ulonglong2 p0 = Abuf[j * 8 + c];
                fma2(a0A, p0.x, wA[2 * c]);     fma2(a0B, p0.x, wB[2 * c]);
                fma2(a0A, p0.y, wA[2 * c + 1]); fma2(a0B, p0.y, wB[2 * c + 1]);
            }
            float xl, xh;
            unpk(Xbuf[j * 32 + lane], xl, xh);
            accx += fmaxf(xl + hsum2(a0A), 0.0f); accy += fmaxf(xh + hsum2(a0B), 0.0f);
        }
        cO += 16;
        if (cO >= cD) {
            float2 o; o.x = accx; o.y = accy;
            ((float2*)g_agg)[(size_t)cN * 32 + lane] = o;
            accx = 0.0f; accy = 0.0f;
            cO = 0; cN++;
            while (cN < nodeEnd) {
                cD = min(g_deg[cN], MAXDEG);
                if (cD > 0) break;
                ((float2*)g_agg)[(size_t)cN * 32 + lane] = zero2;  // deg-0 node
                cN++;
            }
        }
    };

    if (S > 0) {
        stageNext(0);
        for (int s = 0; s < S; s++) {
            if (s + 1 < S) {
                stageNext((s + 1) & 1);
                asm volatile("cp.async.wait_group 1;" ::: "memory");
            } else {
                asm volatile("cp.async.wait_group 0;" ::: "memory");
            }
            __syncwarp();
            computeOne(s & 1);
            __syncwarp();   // reads done before buffer restaged
        }
    }
}

// ---------------- node MLP + fused BN partial stats (R13 config: no reg cap, no spill) -----
#define SH(r, c) ((r) * 64 + ((c) ^ ((r) & 31)))

__global__ void __launch_bounds__(128) mlp_kernel(
    const float* __restrict__ xext, int xsel,
    const float* __restrict__ W1, const float* __restrict__ b1,
    const float* __restrict__ W2, const float* __restrict__ b2, int layer)
{
    __shared__ float sh[128 * 64];
    __shared__ ulonglong2 sW[64 * 16];
    const float* x = sel_x(xext, xsel);
    int tid = threadIdx.x;
    int rowbase = blockIdx.x * 128;

    for (int i = tid; i < 128 * 64; i += 128) {
        int r = i >> 6, c = i & 63;
        float v = 0.0f;
        if (rowbase + r < N_NODES) {
            size_t g = (size_t)(rowbase + r) * HID + c;
            v = x[g] + g_agg[g];
        }
        sh[SH(r, c)] = v;
    }
    for (int i = tid; i < 1024; i += 128) sW[i] = ((const ulonglong2*)W1)[i];
    __syncthreads();

    u64 acc[32];
#pragma unroll
    for (int j = 0; j < 32; j++) acc[j] = ((const u64*)b1)[j];
    for (int k = 0; k < 64; k++) {
        u64 hk = pk(sh[SH(tid, k)]);
#pragma unroll
        for (int j = 0; j < 16; j++) {
            ulonglong2 wv = sW[k * 16 + j];
            fma2(acc[2 * j], hk, wv.x);
            fma2(acc[2 * j + 1], hk, wv.y);
        }
    }
    __syncthreads();
#pragma unroll
    for (int j = 0; j < 32; j++) {
        float lo, hi; unpk(acc[j], lo, hi);
        sh[SH(tid, 2 * j)]     = fmaxf(lo, 0.0f);
        sh[SH(tid, 2 * j + 1)] = fmaxf(hi, 0.0f);
    }
    for (int i = tid; i < 1024; i += 128) sW[i] = ((const ulonglong2*)W2)[i];
    __syncthreads();

#pragma unroll
    for (int j = 0; j < 32; j++) acc[j] = ((const u64*)b2)[j];
    for (int k = 0; k < 64; k++) {
        u64 hk = pk(sh[SH(tid, k)]);
#pragma unroll
        for (int j = 0; j < 16; j++) {
            ulonglong2 wv = sW[k * 16 + j];
            fma2(acc[2 * j], hk, wv.x);
            fma2(acc[2 * j + 1], hk, wv.y);
        }
    }
#pragma unroll
    for (int j = 0; j < 32; j++) {
        float lo, hi; unpk(acc[j], lo, hi);
        sh[SH(tid, 2 * j)]     = lo;
        sh[SH(tid, 2 * j + 1)] = hi;
    }
    __syncthreads();

    for (int i = tid; i < 128 * 64; i += 128) {
        int r = i >> 6, c = i & 63;
        if (rowbase + r < N_NODES)
            g_tmp[(size_t)(rowbase + r) * HID + c] = sh[SH(r, c)];
    }

    {
        float* red = (float*)sW;
        int f = tid & 63, half = tid >> 6;
        float s = 0.0f, s2 = 0.0f;
        int rend = half * 64 + 64;
        for (int r = half * 64; r < rend; r++) {
            if (rowbase + r < N_NODES) {
                float v = sh[SH(r, f)];
                s += v; s2 += v * v;
            }
        }
        red[tid] = s;
        red[128 + tid] = s2;
        __syncthreads();
        if (tid < 64) {
            atomicAdd(&g_stats[layer * 128 + f],      red[tid] + red[tid + 64]);
            atomicAdd(&g_stats[layer * 128 + 64 + f], red[128 + tid] + red[192 + tid]);
        }
    }
}

// ---------------- BN apply + relu -> next layer's x buffer (layers 0,1) --------------------
__global__ void __launch_bounds__(256) bn_kernel(
    int layer, const float* __restrict__ gamma, const float* __restrict__ beta, int outsel)
{
    size_t idx = (size_t)blockIdx.x * 256 + threadIdx.x;
    if (idx >= (size_t)N_NODES * HID) return;
    int f = (int)(idx & 63);
    const float inv = 1.0f / (float)N_NODES;
    float mean = g_stats[layer * 128 + f] * inv;
    float var  = g_stats[layer * 128 + 64 + f] * inv - mean * mean;
    float v = (g_tmp[idx] - mean) * rsqrtf(var + BN_EPS) * __ldg(gamma + f) + __ldg(beta + f);
    float* o = (outsel == 1) ? g_bufA : g_bufB;
    o[idx] = fmaxf(v, 0.0f);
}

// ---------------- output head with fused layer-2 BN (R13 config: no reg cap) ---------------
__global__ void __launch_bounds__(128) out_kernel(
    const float* __restrict__ Wout, const float* __restrict__ bout,
    const float* __restrict__ gamma2, const float* __restrict__ beta2,
    float* __restrict__ out)
{
    __shared__ float sh[128 * 64];
    __shared__ ulonglong2 sW[64 * 16];
    int tid = threadIdx.x;
    int rowbase = blockIdx.x * 128;

    int fc = tid & 63;
    const float inv = 1.0f / (float)N_NODES;
    float mean = g_stats[2 * 128 + fc] * inv;
    float var  = g_stats[2 * 128 + 64 + fc] * inv - mean * mean;
    float rs   = rsqrtf(var + BN_EPS) * __ldg(gamma2 + fc);
    float bt   = __ldg(beta2 + fc);

    for (int i = tid; i < 128 * 64; i += 128) {
        int r = i >> 6, c = i & 63;
        float v = 0.0f;
        if (rowbase + r < N_NODES) {
            float t = g_tmp[(size_t)(rowbase + r) * HID + c];
            v = fmaxf((t - mean) * rs + bt, 0.0f);
        }
        sh[SH(r, c)] = v;
    }
    for (int i = tid; i < 1024; i += 128) sW[i] = ((const ulonglong2*)Wout)[i];
    __syncthreads();

    u64 acc[32];
#pragma unroll
    for (int j = 0; j < 32; j++) acc[j] = ((const u64*)bout)[j];
    for (int k = 0; k < 64; k++) {
        u64 hk = pk(sh[SH(tid, k)]);
#pragma unroll
        for (int j = 0; j < 16; j++) {
            ulonglong2 wv = sW[k * 16 + j];
            fma2(acc[2 * j], hk, wv.x);
            fma2(acc[2 * j + 1], hk, wv.y);
        }
    }
    __syncthreads();
#pragma unroll
    for (int j = 0; j < 32; j++) {
        float lo, hi; unpk(acc[j], lo, hi);
        sh[SH(tid, 2 * j)]     = lo;
        sh[SH(tid, 2 * j + 1)] = hi;
    }
    __syncthreads();
    for (int i = tid; i < 128 * 64; i += 128) {
        int r = i >> 6, c = i & 63;
        if (rowbase + r < N_NODES)
            out[(size_t)(rowbase + r) * HID + c] = sh[SH(r, c)];
    }
}

// ---------------- launch --------------------------------------------------------------------
extern "C" void kernel_launch(void* const* d_in, const int* in_sizes, int n_in,
                              void* d_out, int out_size) {
    const float* x     = (const float*)d_in[0];
    const int*   ei    = (const int*)  d_in[1];
    const float* ea    = (const float*)d_in[2];
    const float* We    = (const float*)d_in[3];
    const float* be    = (const float*)d_in[4];
    const float* W1    = (const float*)d_in[5];
    const float* b1    = (const float*)d_in[6];
    const float* W2    = (const float*)d_in[7];
    const float* b2    = (const float*)d_in[8];
    const float* gamma = (const float*)d_in[9];
    const float* beta  = (const float*)d_in[10];
    const float* Wout  = (const float*)d_in[11];
    const float* bout  = (const float*)d_in[12];
    float* out = (float*)d_out;

    const int AGG_BLOCKS  = N_NODES / (4 * NPW);                 // 3125 (exact)
    const int MLP_BLOCKS  = (N_NODES + 127) / 128;
    const int BN_BLOCKS   = (int)(((size_t)N_NODES * HID + 255) / 256);
    const int CSR_BLOCKS  = (N_EDGES * 8 + 255) / 256;

    zero_kernel<<<(N_NODES + 255) / 256, 256>>>();
    csr_perm_kernel<<<CSR_BLOCKS, 256>>>(ei, ea);

    agg_kernel<<<AGG_BLOCKS, 128>>>(x, 0, We + 0 * EDIM * HID, be + 0 * HID);
    mlp_kernel<<<MLP_BLOCKS, 128>>>(x, 0, W1 + 0 * HID * HID, b1 + 0 * HID,
                                    W2 + 0 * HID * HID, b2 + 0 * HID, 0);
    bn_kernel<<<BN_BLOCKS, 256>>>(0, gamma + 0 * HID, beta + 0 * HID, 1);

    agg_kernel<<<AGG_BLOCKS, 128>>>(x, 1, We + 1 * EDIM * HID, be + 1 * HID);
    mlp_kernel<<<MLP_BLOCKS, 128>>>(x, 1, W1 + 1 * HID * HID, b1 + 1 * HID,
                                    W2 + 1 * HID * HID, b2 + 1 * HID, 1);
    bn_kernel<<<BN_BLOCKS, 256>>>(1, gamma + 1 * HID, beta + 1 * HID, 2);

    agg_kernel<<<AGG_BLOCKS, 128>>>(x, 2, We + 2 * EDIM * HID, be + 2 * HID);
    mlp_kernel<<<MLP_BLOCKS, 128>>>(x, 2, W1 + 2 * HID * HID, b1 + 2 * HID,
                                    W2 + 2 * HID * HID, b2 + 2 * HID, 2);

    out_kernel<<<MLP_BLOCKS, 128>>>(Wout, bout, gamma + 2 * HID, beta + 2 * HID, out);
}

// round 16
// speedup vs baseline: 2.9810x; 1.0162x over previous
#include <cuda_runtime.h>
#include <math_constants.h>

#define N_NODES 100000
#define N_EDGES 1600000
#define HID 64
#define EDIM 32
#define MAXDEG 64
#define N_LAYERS 3
#define BN_EPS 1e-5f
#define NPW 8   // nodes per warp in agg

typedef unsigned long long u64;

// ---------------- scratch (static device globals; no allocation) ----------------
__device__ float g_agg[(size_t)N_NODES * HID];
__device__ float g_tmp[(size_t)N_NODES * HID];
__device__ float g_stats[N_LAYERS * 2 * HID];
__device__ int   g_deg[N_NODES];
__device__ int   g_src[(size_t)N_NODES * MAXDEG];
__device__ float g_attr_p[(size_t)N_NODES * MAXDEG * EDIM];

// ---------------- packed f32x2 helpers ----------------
__device__ __forceinline__ u64 pk(float s) {
    u64 r; asm("mov.b64 %0, {%1, %1};" : "=l"(r) : "f"(s)); return r;
}
__device__ __forceinline__ u64 pk2(float a, float b) {
    u64 r; asm("mov.b64 %0, {%1, %2};" : "=l"(r) : "f"(a), "f"(b)); return r;
}
__device__ __forceinline__ void fma2(u64& d, u64 a, u64 b) {
    asm("fma.rn.f32x2 %0, %1, %2, %0;" : "+l"(d) : "l"(a), "l"(b));
}
__device__ __forceinline__ void unpk(u64 v, float& lo, float& hi) {
    asm("mov.b64 {%0, %1}, %2;" : "=f"(lo), "=f"(hi) : "l"(v));
}
__device__ __forceinline__ float hsum2(u64 v) {
    float lo, hi; unpk(v, lo, hi); return lo + hi;
}

// ---------------- cp.async helpers ----------------
__device__ __forceinline__ void cp16(unsigned dst, const void* src) {
    asm volatile("cp.async.cg.shared.global [%0], [%1], 16;" :: "r"(dst), "l"(src));
}
__device__ __forceinline__ void cp_commit() { asm volatile("cp.async.commit_group;"); }

// ---------------- init ----------------
__global__ void zero_kernel() {
    int i = blockIdx.x * blockDim.x + threadIdx.x;
    if (i < N_NODES) g_deg[i] = 0;
    if (i < N_LAYERS * 2 * HID) g_stats[i] = 0.0f;
}

// ---------------- CSR build + attr permutation fused (once per launch) ----------------
__global__ void __launch_bounds__(256) csr_perm_kernel(
    const int* __restrict__ ei, const float* __restrict__ attr)
{
    int t = blockIdx.x * 256 + threadIdx.x;
    int e = t >> 3, q = t & 7;
    if (e >= N_EDGES) return;
    int dst = 0, slot = 0;
    if (q == 0) {
        dst = ei[N_EDGES + e];
        slot = atomicAdd(&g_deg[dst], 1);
    }
    dst  = __shfl_sync(0xffffffffu, dst, 0, 8);
    slot = __shfl_sync(0xffffffffu, slot, 0, 8);
    if (slot < MAXDEG) {
        int d = dst * MAXDEG + slot;
        if (q == 0) g_src[d] = ei[e];
        ((float4*)g_attr_p)[(size_t)d * 8 + q] =
            __ldg((const float4*)attr + (size_t)e * 8 + q);
    }
}

// ---------------- edge aggregation: warp owns NPW nodes; cross-node sub-chunk pipeline -----
// x source: raw input (prevLayer<0) or g_tmp with fused BN affine + relu (prevLayer>=0).
__global__ void __launch_bounds__(128, 4) agg_kernel(
    const float* __restrict__ xext, int prevLayer,
    const float* __restrict__ gammaP, const float* __restrict__ betaP,
    const float* __restrict__ We, const float* __restrict__ be)
{
    __shared__ __align__(16) float sAttr[4][2][16 * 32];   // 2KB / buf / warp
    __shared__ __align__(16) float sX[4][2][16 * 64];      // 4KB / buf / warp

    int wid  = threadIdx.x >> 5;
    int lane = threadIdx.x & 31;
    int nodeBeg = (blockIdx.x * 4 + wid) * NPW;
    int nodeEnd = nodeBeg + NPW;

    int fA = 2 * lane, fB = 2 * lane + 1;

    // fused-BN affine for the gathered x values (identity for layer 0)
    float rsA = 1.0f, btA = 0.0f, rsB = 1.0f, btB = 0.0f, clampLo = -CUDART_INF_F;
    const char* xg;
    if (prevLayer >= 0) {
        const float inv = 1.0f / (float)N_NODES;
        float mA = g_stats[prevLayer * 128 + fA] * inv;
        float vA = g_stats[prevLayer * 128 + 64 + fA] * inv - mA * mA;
        rsA = rsqrtf(vA + BN_EPS) * __ldg(gammaP + fA);
        btA = __ldg(betaP + fA) - mA * rsA;
        float mB = g_stats[prevLayer * 128 + fB] * inv;
        float vB = g_stats[prevLayer * 128 + 64 + fB] * inv - mB * mB;
        rsB = rsqrtf(vB + BN_EPS) * __ldg(gammaP + fB);
        btB = __ldg(betaP + fB) - mB * rsB;
        clampLo = 0.0f;
        xg = (const char*)g_tmp;
    } else {
        xg = (const char*)xext;
    }

    u64 wA[16], wB[16];
#pragma unroll
    for (int kp = 0; kp < 16; kp++) {
        wA[kp] = pk2(__ldg(We + (2 * kp) * HID + fA), __ldg(We + (2 * kp + 1) * HID + fA));
        wB[kp] = pk2(__ldg(We + (2 * kp) * HID + fB), __ldg(We + (2 * kp + 1) * HID + fB));
    }
    u64 biasA = pk2(__ldg(be + fA), 0.0f);
    u64 biasB = pk2(__ldg(be + fB), 0.0f);

    // total sub-chunks for this warp (lane-parallel count + butterfly reduce)
    int dd = (lane < NPW) ? min(g_deg[nodeBeg + lane], MAXDEG) : 0;
    int S = (dd + 15) >> 4;
#pragma unroll
    for (int o = 16; o > 0; o >>= 1) S += __shfl_xor_sync(0xffffffffu, S, o);

    unsigned abuf0 = (unsigned)__cvta_generic_to_shared(&sAttr[wid][0][0]);
    unsigned abuf1 = (unsigned)__cvta_generic_to_shared(&sAttr[wid][1][0]);
    unsigned xbuf0 = (unsigned)__cvta_generic_to_shared(&sX[wid][0][0]);
    unsigned xbuf1 = (unsigned)__cvta_generic_to_shared(&sX[wid][1][0]);

    // ---- stage cursor ----
    int sN = nodeBeg, sO = 0, sD = 0;
    while (sN < nodeEnd) { sD = min(g_deg[sN], MAXDEG); if (sD > 0) break; sN++; }

    auto stageNext = [&](int b) {
        int cnt = sD - sO; if (cnt > 16) cnt = 16;
        unsigned ab = b ? abuf1 : abuf0;
        unsigned xb = b ? xbuf1 : xbuf0;
        const char* asrc = (const char*)g_attr_p + ((size_t)sN * MAXDEG + sO) * 128;
        int words = cnt * 8;
        for (int i = lane; i < words; i += 32)
            cp16(ab + i * 16, asrc + i * 16);
        int p = lane >> 1, hh = lane & 1;        // 2 lanes per edge, 128B each
        if (p < cnt) {
            int src = g_src[sN * MAXDEG + sO + p];
            const char* xs = xg + (size_t)src * 256 + hh * 128;
            unsigned xd = xb + p * 256 + hh * 128;
#pragma unroll
            for (int i = 0; i < 8; i++) cp16(xd + i * 16, xs + i * 16);
        }
        cp_commit();
        sO += 16;
        if (sO >= sD) {
            sO = 0; sN++;
            while (sN < nodeEnd) { sD = min(g_deg[sN], MAXDEG); if (sD > 0) break; sN++; }
        }
    };

    // ---- compute cursor ----
    float accx = 0.0f, accy = 0.0f;
    float2 zero2; zero2.x = 0.0f; zero2.y = 0.0f;
    int cN = nodeBeg, cO = 0, cD = 0;
    while (cN < nodeEnd) {
        cD = min(g_deg[cN], MAXDEG);
        if (cD > 0) break;
        ((float2*)g_agg)[(size_t)cN * 32 + lane] = zero2;   // deg-0 node
        cN++;
    }

    auto xfA = [&](float t) { return fmaxf(fmaf(t, rsA, btA), clampLo); };
    auto xfB = [&](float t) { return fmaxf(fmaf(t, rsB, btB), clampLo); };

    auto computeOne = [&](int b) {
        int cnt = cD - cO; if (cnt > 16) cnt = 16;
        const ulonglong2* Abuf = (const ulonglong2*)&sAttr[wid][b][0];
        const u64* Xbuf = (const u64*)&sX[wid][b][0];
        int j = 0;
        for (; j + 4 <= cnt; j += 4) {
            u64 a0A = biasA, a0B = biasB, a1A = biasA, a1B = biasB;
            u64 a2A = biasA, a2B = biasB, a3A = biasA, a3B = biasB;
#pragma unroll
            for (int c = 0; c < 8; c++) {
                ulonglong2 p0 = Abuf[(j + 0) * 8 + c];
                ulonglong2 p1 = Abuf[(j + 1) * 8 + c];
                ulonglong2 p2 = Abuf[(j + 2) * 8 + c];
                ulonglong2 p3 = Abuf[(j + 3) * 8 + c];
                fma2(a0A, p0.x, wA[2 * c]);     fma2(a0B, p0.x, wB[2 * c]);
                fma2(a0A, p0.y, wA[2 * c + 1]); fma2(a0B, p0.y, wB[2 * c + 1]);
                fma2(a1A, p1.x, wA[2 * c]);     fma2(a1B, p1.x, wB[2 * c]);
                fma2(a1A, p1.y, wA[2 * c + 1]); fma2(a1B, p1.y, wB[2 * c + 1]);
                fma2(a2A, p2.x, wA[2 * c]);     fma2(a2B, p2.x, wB[2 * c]);
                fma2(a2A, p2.y, wA[2 * c + 1]); fma2(a2B, p2.y, wB[2 * c + 1]);
                fma2(a3A, p3.x, wA[2 * c]);     fma2(a3B, p3.x, wB[2 * c]);
                fma2(a3A, p3.y, wA[2 * c + 1]); fma2(a3B, p3.y, wB[2 * c + 1]);
            }
            float xl, xh;
            unpk(Xbuf[(j + 0) * 32 + lane], xl, xh);
            accx += fmaxf(xfA(xl) + hsum2(a0A), 0.0f); accy += fmaxf(xfB(xh) + hsum2(a0B), 0.0f);
            unpk(Xbuf[(j + 1) * 32 + lane], xl, xh);
            accx += fmaxf(xfA(xl) + hsum2(a1A), 0.0f); accy += fmaxf(xfB(xh) + hsum2(a1B), 0.0f);
            unpk(Xbuf[(j + 2) * 32 + lane], xl, xh);
            accx += fmaxf(xfA(xl) + hsum2(a2A), 0.0f); accy += fmaxf(xfB(xh) + hsum2(a2B), 0.0f);
            unpk(Xbuf[(j + 3) * 32 + lane], xl, xh);
            accx += fmaxf(xfA(xl) + hsum2(a3A), 0.0f); accy += fmaxf(xfB(xh) + hsum2(a3B), 0.0f);
        }
        for (; j < cnt; j++) {
            u64 a0A = biasA, a0B = biasB;
#pragma unroll
            for (int c = 0; c < 8; c++) {
                ulonglong2 p0 = Abuf[j * 8 + c];
                fma2(a0A, p0.x, wA[2 * c]);     fma2(a0B, p0.x, wB[2 * c]);
                fma2(a0A, p0.y, wA[2 * c + 1]); fma2(a0B, p0.y, wB[2 * c + 1]);
            }
            float xl, xh;
            unpk(Xbuf[j * 32 + lane], xl, xh);
            accx += fmaxf(xfA(xl) + hsum2(a0A), 0.0f); accy += fmaxf(xfB(xh) + hsum2(a0B), 0.0f);
        }
        cO += 16;
        if (cO >= cD) {
            float2 o; o.x = accx; o.y = accy;
            ((float2*)g_agg)[(size_t)cN * 32 + lane] = o;
            accx = 0.0f; accy = 0.0f;
            cO = 0; cN++;
            while (cN < nodeEnd) {
                cD = min(g_deg[cN], MAXDEG);
                if (cD > 0) break;
                ((float2*)g_agg)[(size_t)cN * 32 + lane] = zero2;  // deg-0 node
                cN++;
            }
        }
    };

    if (S > 0) {
        stageNext(0);
        for (int s = 0; s < S; s++) {
            if (s + 1 < S) {
                stageNext((s + 1) & 1);
                asm volatile("cp.async.wait_group 1;" ::: "memory");
            } else {
                asm volatile("cp.async.wait_group 0;" ::: "memory");
            }
            __syncwarp();
            computeOne(s & 1);
            __syncwarp();   // reads done before buffer restaged
        }
    }
}

// ---------------- node MLP + fused input-BN + fused BN partial stats -----------------------
// Staging applies the previous layer's BN affine + relu on the fly (identity for layer 0).
#define SH(r, c) ((r) * 64 + ((c) ^ ((r) & 31)))

__global__ void __launch_bounds__(128) mlp_kernel(
    const float* __restrict__ xext, int prevLayer,
    const float* __restrict__ gammaP, const float* __restrict__ betaP,
    const float* __restrict__ W1, const float* __restrict__ b1,
    const float* __restrict__ W2, const float* __restrict__ b2, int layer)
{
    __shared__ float sh[128 * 64];
    __shared__ ulonglong2 sW[64 * 16];
    int tid = threadIdx.x;
    int rowbase = blockIdx.x * 128;

    // BN affine for this thread's fixed staging column (tid & 63)
    int fc = tid & 63;
    float rs = 1.0f, bt = 0.0f, clampLo = -CUDART_INF_F;
    const float* xsrc;
    if (prevLayer >= 0) {
        const float inv = 1.0f / (float)N_NODES;
        float m = g_stats[prevLayer * 128 + fc] * inv;
        float v = g_stats[prevLayer * 128 + 64 + fc] * inv - m * m;
        rs = rsqrtf(v + BN_EPS) * __ldg(gammaP + fc);
        bt = __ldg(betaP + fc) - m * rs;
        clampLo = 0.0f;
        xsrc = g_tmp;
    } else {
        xsrc = xext;
    }

    for (int i = tid; i < 128 * 64; i += 128) {
        int r = i >> 6, c = i & 63;   // c == fc for all i of this thread
        float v = 0.0f;
        if (rowbase + r < N_NODES) {
            size_t g = (size_t)(rowbase + r) * HID + c;
            v = fmaxf(fmaf(xsrc[g], rs, bt), clampLo) + g_agg[g];
        }
        sh[SH(r, c)] = v;
    }
    for (int i = tid; i < 1024; i += 128) sW[i] = ((const ulonglong2*)W1)[i];
    __syncthreads();

    u64 acc[32];
#pragma unroll
    for (int j = 0; j < 32; j++) acc[j] = ((const u64*)b1)[j];
    for (int k = 0; k < 64; k++) {
        u64 hk = pk(sh[SH(tid, k)]);
#pragma unroll
        for (int j = 0; j < 16; j++) {
            ulonglong2 wv = sW[k * 16 + j];
            fma2(acc[2 * j], hk, wv.x);
            fma2(acc[2 * j + 1], hk, wv.y);
        }
    }
    __syncthreads();
#pragma unroll
    for (int j = 0; j < 32; j++) {
        float lo, hi; unpk(acc[j], lo, hi);
        sh[SH(tid, 2 * j)]     = fmaxf(lo, 0.0f);
        sh[SH(tid, 2 * j + 1)] = fmaxf(hi, 0.0f);
    }
    for (int i = tid; i < 1024; i += 128) sW[i] = ((const ulonglong2*)W2)[i];
    __syncthreads();

#pragma unroll
    for (int j = 0; j < 32; j++) acc[j] = ((const u64*)b2)[j];
    for (int k = 0; k < 64; k++) {
        u64 hk = pk(sh[SH(tid, k)]);
#pragma unroll
        for (int j = 0; j < 16; j++) {
            ulonglong2 wv = sW[k * 16 + j];
            fma2(acc[2 * j], hk, wv.x);
            fma2(acc[2 * j + 1], hk, wv.y);
        }
    }
#pragma unroll
    for (int j = 0; j < 32; j++) {
        float lo, hi; unpk(acc[j], lo, hi);
        sh[SH(tid, 2 * j)]     = lo;
        sh[SH(tid, 2 * j + 1)] = hi;
    }
    __syncthreads();

    for (int i = tid; i < 128 * 64; i += 128) {
        int r = i >> 6, c = i & 63;
        if (rowbase + r < N_NODES)
            g_tmp[(size_t)(rowbase + r) * HID + c] = sh[SH(r, c)];
    }

    {
        float* red = (float*)sW;
        int f = tid & 63, half = tid >> 6;
        float s = 0.0f, s2 = 0.0f;
        int rend = half * 64 + 64;
        for (int r = half * 64; r < rend; r++) {
            if (rowbase + r < N_NODES) {
                float v = sh[SH(r, f)];
                s += v; s2 += v * v;
            }
        }
        red[tid] = s;
        red[128 + tid] = s2;
        __syncthreads();
        if (tid < 64) {
            atomicAdd(&g_stats[layer * 128 + f],      red[tid] + red[tid + 64]);
            atomicAdd(&g_stats[layer * 128 + 64 + f], red[128 + tid] + red[192 + tid]);
        }
    }
}

// ---------------- output head with fused layer-2 BN ----------------------------------------
__global__ void __launch_bounds__(128) out_kernel(
    const float* __restrict__ Wout, const float* __restrict__ bout,
    const float* __restrict__ gamma2, const float* __restrict__ beta2,
    float* __restrict__ out)
{
    __shared__ float sh[128 * 64];
    __shared__ ulonglong2 sW[64 * 16];
    int tid = threadIdx.x;
    int rowbase = blockIdx.x * 128;

    int fc = tid & 63;
    const float inv = 1.0f / (float)N_NODES;
    float mean = g_stats[2 * 128 + fc] * inv;
    float var  = g_stats[2 * 128 + 64 + fc] * inv - mean * mean;
    float rs   = rsqrtf(var + BN_EPS) * __ldg(gamma2 + fc);
    float bt   = __ldg(beta2 + fc);

    for (int i = tid; i < 128 * 64; i += 128) {
        int r = i >> 6, c = i & 63;
        float v = 0.0f;
        if (rowbase + r < N_NODES) {
            float t = g_tmp[(size_t)(rowbase + r) * HID + c];
            v = fmaxf((t - mean) * rs + bt, 0.0f);
        }
        sh[SH(r, c)] = v;
    }
    for (int i = tid; i < 1024; i += 128) sW[i] = ((const ulonglong2*)Wout)[i];
    __syncthreads();

    u64 acc[32];
#pragma unroll
    for (int j = 0; j < 32; j++) acc[j] = ((const u64*)bout)[j];
    for (int k = 0; k < 64; k++) {
        u64 hk = pk(sh[SH(tid, k)]);
#pragma unroll
        for (int j = 0; j < 16; j++) {
            ulonglong2 wv = sW[k * 16 + j];
            fma2(acc[2 * j], hk, wv.x);
            fma2(acc[2 * j + 1], hk, wv.y);
        }
    }
    __syncthreads();
#pragma unroll
    for (int j = 0; j < 32; j++) {
        float lo, hi; unpk(acc[j], lo, hi);
        sh[SH(tid, 2 * j)]     = lo;
        sh[SH(tid, 2 * j + 1)] = hi;
    }
    __syncthreads();
    for (int i = tid; i < 128 * 64; i += 128) {
        int r = i >> 6, c = i & 63;
        if (rowbase + r < N_NODES)
            out[(size_t)(rowbase + r) * HID + c] = sh[SH(r, c)];
    }
}

// ---------------- launch --------------------------------------------------------------------
extern "C" void kernel_launch(void* const* d_in, const int* in_sizes, int n_in,
                              void* d_out, int out_size) {
    const float* x     = (const float*)d_in[0];
    const int*   ei    = (const int*)  d_in[1];
    const float* ea    = (const float*)d_in[2];
    const float* We    = (const float*)d_in[3];
    const float* be    = (const float*)d_in[4];
    const float* W1    = (const float*)d_in[5];
    const float* b1    = (const float*)d_in[6];
    const float* W2    = (const float*)d_in[7];
    const float* b2    = (const float*)d_in[8];
    const float* gamma = (const float*)d_in[9];
    const float* beta  = (const float*)d_in[10];
    const float* Wout  = (const float*)d_in[11];
    const float* bout  = (const float*)d_in[12];
    float* out = (float*)d_out;

    const int AGG_BLOCKS  = N_NODES / (4 * NPW);                 // 3125 (exact)
    const int MLP_BLOCKS  = (N_NODES + 127) / 128;
    const int CSR_BLOCKS  = (N_EDGES * 8 + 255) / 256;

    zero_kernel<<<(N_NODES + 255) / 256, 256>>>();
    csr_perm_kernel<<<CSR_BLOCKS, 256>>>(ei, ea);

    // layer 0: x raw
    agg_kernel<<<AGG_BLOCKS, 128>>>(x, -1, nullptr, nullptr,
                                    We + 0 * EDIM * HID, be + 0 * HID);
    mlp_kernel<<<MLP_BLOCKS, 128>>>(x, -1, nullptr, nullptr,
                                    W1 + 0 * HID * HID, b1 + 0 * HID,
                                    W2 + 0 * HID * HID, b2 + 0 * HID, 0);

    // layer 1: x = relu(bn0(g_tmp)) applied at consumption
    agg_kernel<<<AGG_BLOCKS, 128>>>(x, 0, gamma + 0 * HID, beta + 0 * HID,
                                    We + 1 * EDIM * HID, be + 1 * HID);
    mlp_kernel<<<MLP_BLOCKS, 128>>>(x, 0, gamma + 0 * HID, beta + 0 * HID,
                                    W1 + 1 * HID * HID, b1 + 1 * HID,
                                    W2 + 1 * HID * HID, b2 + 1 * HID, 1);

    // layer 2: x = relu(bn1(g_tmp))
    agg_kernel<<<AGG_BLOCKS, 128>>>(x, 1, gamma + 1 * HID, beta + 1 * HID,
                                    We + 2 * EDIM * HID, be + 2 * HID);
    mlp_kernel<<<MLP_BLOCKS, 128>>>(x, 1, gamma + 1 * HID, beta + 1 * HID,
                                    W1 + 2 * HID * HID, b1 + 2 * HID,
                                    W2 + 2 * HID * HID, b2 + 2 * HID, 2);

    // output head: relu(bn2(g_tmp)) @ Wout + bout
    out_kernel<<<MLP_BLOCKS, 128>>>(Wout, bout, gamma + 2 * HID, beta + 2 * HID, out);
}